// round 6
// baseline (speedup 1.0000x reference)
#include <cuda_runtime.h>
#include <cuda_bf16.h>
#include <cstdint>

#define MTOT 131072
#define SWZ(o) ((o) ^ (((o) >> 3) & 0x70))

// -------- device scratch (allocation-free) --------
__device__ float g_act0[(size_t)512 * MTOT];
__device__ float g_act1[(size_t)512 * MTOT];
__device__ float g_ds[MTOT];
__device__ unsigned short g_whi[1114112];
__device__ unsigned short g_wlo[1114112];

__device__ __forceinline__ uint32_t s2u(const void* p) {
    uint32_t a;
    asm("{ .reg .u64 t; cvta.to.shared.u64 t, %1; cvt.u32.u64 %0, t; }" : "=r"(a) : "l"(p));
    return a;
}
__device__ __forceinline__ void ldsm4(uint32_t* r, uint32_t a) {
    asm volatile("ldmatrix.sync.aligned.m8n8.x4.shared.b16 {%0,%1,%2,%3}, [%4];"
                 : "=r"(r[0]), "=r"(r[1]), "=r"(r[2]), "=r"(r[3]) : "r"(a));
}
__device__ __forceinline__ void mma16816(float* c, const uint32_t* a, uint32_t b0, uint32_t b1) {
    asm volatile("mma.sync.aligned.m16n8k16.row.col.f32.bf16.bf16.f32 "
                 "{%0,%1,%2,%3},{%4,%5,%6,%7},{%8,%9},{%0,%1,%2,%3};"
                 : "+f"(c[0]), "+f"(c[1]), "+f"(c[2]), "+f"(c[3])
                 : "r"(a[0]), "r"(a[1]), "r"(a[2]), "r"(a[3]), "r"(b0), "r"(b1));
}
__device__ __forceinline__ uint32_t packhi(float f0, float f1, float& h0f, float& h1f) {
    __nv_bfloat16 h0 = __float2bfloat16(f0), h1 = __float2bfloat16(f1);
    h0f = __bfloat162float(h0);
    h1f = __bfloat162float(h1);
    return (uint32_t)__bfloat16_as_ushort(h0) | ((uint32_t)__bfloat16_as_ushort(h1) << 16);
}
__device__ __forceinline__ uint32_t packlo(float r0, float r1) {
    __nv_bfloat16 l0 = __float2bfloat16(r0), l1 = __float2bfloat16(r1);
    return (uint32_t)__bfloat16_as_ushort(l0) | ((uint32_t)__bfloat16_as_ushort(l1) << 16);
}

// -------- weight prep: bf16 hi/lo split, pre-swizzled per (kchunk, nblock) 16KB tiles --------
// W[kin,512] row-major.  tile = [128 n][64 k] bf16 SW128, image index (kc*4+nb).
__global__ void prep_w(const float* __restrict__ W,
                       unsigned short* __restrict__ dh, unsigned short* __restrict__ dl) {
    int idx = blockIdx.x * 256 + threadIdx.x;
    int n = idx & 511, k = idx >> 9;
    float f = W[idx];
    __nv_bfloat16 h = __float2bfloat16(f);
    float hf = __bfloat162float(h);
    __nv_bfloat16 l = __float2bfloat16(f - hf);
    int nb = n >> 7, nl = n & 127, kc = k >> 6, kl = k & 63;
    uint32_t off = (uint32_t)(kc * 4 + nb) * 8192u + (SWZ((uint32_t)(nl * 128 + kl * 2)) >> 1);
    dh[off] = __bfloat16_as_ushort(h);
    dl[off] = __bfloat16_as_ushort(l);
}

// -------- GEMM layer: out[c][r] = tanh( A_row(r) . W[:,c] + bias[c] ), col-major out --------
// mode=1: A from koopman (B,L,D): A[r][k] = koop[(r>>6)*4096 + k*64 + (r&63)]
// mode=0: A from col-major activations: A[r][k] = in[k*MTOT + r]
__global__ void __launch_bounds__(256, 2) gemm_layer(
    const float* __restrict__ in, int mode, int kin,
    const unsigned short* __restrict__ wh, const unsigned short* __restrict__ wl,
    const float* __restrict__ bias, float* __restrict__ out) {
    extern __shared__ char sm[];
    const uint32_t sbase = s2u(sm);
    const uint32_t SAHI = sbase, SALO = sbase + 16384u, SBHI = sbase + 32768u, SBLO = sbase + 49152u;

    const int tid = threadIdx.x, lane = tid & 31, wid = tid >> 5;
    const int wm = wid & 3, wn = wid >> 2;
    const int mbase = blockIdx.x * 128;
    const int nb = blockIdx.y;

    float acc[2][8][4];
#pragma unroll
    for (int t = 0; t < 2; t++)
#pragma unroll
        for (int o = 0; o < 8; o++)
#pragma unroll
            for (int q = 0; q < 4; q++) acc[t][o][q] = 0.f;

    const int a_row = wm * 32 + (lane & 15);
    const int a_kh = (lane >> 4) * 16;                               // bytes
    const int b_nrow = wn * 64 + (lane & 7) + ((lane >> 4) << 3);
    const int b_kh = ((lane >> 3) & 1) * 16;                         // bytes

    const int nchunk = kin >> 6;
    for (int kc = 0; kc < nchunk; kc++) {
        // ---- stage B: linear copy of pre-swizzled 16KB hi + 16KB lo ----
        {
            const uint4* srch = (const uint4*)(wh + (size_t)(kc * 4 + nb) * 8192);
            const uint4* srcl = (const uint4*)(wl + (size_t)(kc * 4 + nb) * 8192);
            uint4* dsth = (uint4*)(sm + 32768);
            uint4* dstl = (uint4*)(sm + 49152);
#pragma unroll
            for (int i = 0; i < 4; i++) {
                dsth[tid + i * 256] = srch[tid + i * 256];
                dstl[tid + i * 256] = srcl[tid + i * 256];
            }
        }
        // ---- stage A: 128 rows x 64 k, hi/lo split, STS.128 ----
#pragma unroll
        for (int it = 0; it < 4; it++) {
            int p = it * 256 + tid;          // 0..1023
            int row = p & 127, kg = p >> 7;  // kg 0..7 (8 k each)
            int k0 = kc * 64 + kg * 8;
            int r = mbase + row;
            float f[8];
            if (mode) {
                const float* s = in + ((r >> 6) * 4096 + (r & 63));
#pragma unroll
                for (int j = 0; j < 8; j++) f[j] = s[(k0 + j) * 64];
            } else {
#pragma unroll
                for (int j = 0; j < 8; j++) f[j] = in[(size_t)(k0 + j) * MTOT + r];
            }
            uint32_t hi[4], lo[4];
#pragma unroll
            for (int j = 0; j < 4; j++) {
                float h0f, h1f;
                hi[j] = packhi(f[2 * j], f[2 * j + 1], h0f, h1f);
                lo[j] = packlo(f[2 * j] - h0f, f[2 * j + 1] - h1f);
            }
            uint32_t off = SWZ((uint32_t)(row * 128 + kg * 16));
            *(uint4*)(sm + off) = make_uint4(hi[0], hi[1], hi[2], hi[3]);
            *(uint4*)(sm + 16384 + off) = make_uint4(lo[0], lo[1], lo[2], lo[3]);
        }
        __syncthreads();

        // ---- MMA: 3-term hi/lo over this 64-K chunk ----
#pragma unroll
        for (int kk = 0; kk < 4; kk++) {
            uint32_t ah[2][4], al[2][4];
#pragma unroll
            for (int t = 0; t < 2; t++) {
                uint32_t ro = (uint32_t)((a_row + t * 16) * 128 + kk * 32 + a_kh);
                ldsm4(ah[t], SAHI + SWZ(ro));
                ldsm4(al[t], SALO + SWZ(ro));
            }
#pragma unroll
            for (int g = 0; g < 4; g++) {
                uint32_t ro = (uint32_t)((b_nrow + g * 16) * 128 + kk * 32 + b_kh);
                uint32_t bh[4], bl[4];
                ldsm4(bh, SBHI + SWZ(ro));
#pragma unroll
                for (int t = 0; t < 2; t++) {
                    mma16816(acc[t][2 * g], ah[t], bh[0], bh[1]);
                    mma16816(acc[t][2 * g + 1], ah[t], bh[2], bh[3]);
                    mma16816(acc[t][2 * g], al[t], bh[0], bh[1]);
                    mma16816(acc[t][2 * g + 1], al[t], bh[2], bh[3]);
                }
                ldsm4(bl, SBLO + SWZ(ro));
#pragma unroll
                for (int t = 0; t < 2; t++) {
                    mma16816(acc[t][2 * g], ah[t], bl[0], bl[1]);
                    mma16816(acc[t][2 * g + 1], ah[t], bl[2], bl[3]);
                }
            }
        }
        __syncthreads();
    }

    // ---- epilogue: bias + tanh, col-major store ----
    const int gcolbase = nb * 128 + wn * 64;
#pragma unroll
    for (int t = 0; t < 2; t++) {
        int r0 = mbase + wm * 32 + t * 16 + (lane >> 2);
#pragma unroll
        for (int o = 0; o < 8; o++) {
            int c0 = gcolbase + o * 8 + (lane & 3) * 2;
            float b0v = bias[c0], b1v = bias[c0 + 1];
            out[(size_t)c0 * MTOT + r0] = tanhf(acc[t][o][0] + b0v);
            out[(size_t)(c0 + 1) * MTOT + r0] = tanhf(acc[t][o][1] + b1v);
            out[(size_t)c0 * MTOT + r0 + 8] = tanhf(acc[t][o][2] + b0v);
            out[(size_t)(c0 + 1) * MTOT + r0 + 8] = tanhf(acc[t][o][3] + b1v);
        }
    }
}

// -------- layer-4 diagonal + final combine --------
__global__ void diag_kernel(const float* __restrict__ h3, const float* __restrict__ W4,
                            const float* __restrict__ b4, const float* __restrict__ x,
                            float* __restrict__ ds, float* __restrict__ out, int mode) {
    int r = blockIdx.x * 256 + threadIdx.x;
    int i = r & 63;
    float acc = 0.f;
#pragma unroll 8
    for (int c = 0; c < 512; c++)
        acc += h3[(size_t)c * MTOT + r] * W4[c * 64 + i];
    acc += b4[i];
    if (mode == 0) ds[r] = acc;
    else out[r] = (x[r] - acc) * expf(-ds[r]);
}

extern "C" void kernel_launch(void* const* d_in, const int* in_sizes, int n_in,
                              void* d_out, int out_size) {
    const float* x = (const float*)d_in[0];
    const float* koop = (const float*)d_in[1];
    const float *W[8], *Bs[8];
    for (int i = 0; i < 8; i++) {
        W[i] = (const float*)d_in[2 + 2 * i];
        Bs[i] = (const float*)d_in[3 + 2 * i];
    }
    unsigned short *wh, *wl;
    float *a0, *a1, *ds;
    cudaGetSymbolAddress((void**)&wh, g_whi);
    cudaGetSymbolAddress((void**)&wl, g_wlo);
    cudaGetSymbolAddress((void**)&a0, g_act0);
    cudaGetSymbolAddress((void**)&a1, g_act1);
    cudaGetSymbolAddress((void**)&ds, g_ds);
    cudaFuncSetAttribute(gemm_layer, cudaFuncAttributeMaxDynamicSharedMemorySize, 65536);

    const int off[6] = {0, 32768, 294912, 557056, 589824, 851968};
    const float* wsrc[6] = {W[0], W[1], W[2], W[4], W[5], W[6]};
    for (int i = 0; i < 6; i++) {
        int kin = (i % 3 == 0) ? 64 : 512;
        prep_w<<<kin * 512 / 256, 256>>>(wsrc[i], wh + off[i], wl + off[i]);
    }
    dim3 grid(1024, 4);
    for (int chain = 0; chain < 2; chain++) {
        for (int l = 0; l < 3; l++) {
            const float* in = (l == 0) ? koop : ((l == 1) ? a0 : a1);
            float* o = (l == 1) ? a1 : a0;
            int oi = chain * 3 + l;
            gemm_layer<<<grid, 256, 65536>>>(in, (l == 0) ? 1 : 0, (l == 0) ? 64 : 512,
                                             wh + off[oi], wl + off[oi],
                                             Bs[chain * 4 + l], o);
        }
        diag_kernel<<<512, 256>>>(a0, W[chain * 4 + 3], Bs[chain * 4 + 3], x, ds,
                                  (float*)d_out, chain);
    }
}

// round 7
// speedup vs baseline: 1.2789x; 1.2789x over previous
#include <cuda_runtime.h>
#include <cuda_bf16.h>
#include <cstdint>

#define MTOT 131072
#define SWZ(o) ((o) ^ (((o) >> 3) & 0x70))
#define SMEMSZ 131584

// -------- device scratch (allocation-free) --------
__device__ float g_act[(size_t)512 * MTOT];            // h3 fp32 col-major
__device__ float g_ds[MTOT];
__device__ unsigned short g_whi[1114112], g_wlo[1114112];
__device__ unsigned short g_zhi[8388608], g_zlo[8388608];       // Z images (K=64)
__device__ unsigned short g_h0a[67108864], g_h0b[67108864];     // h1 images hi/lo
__device__ unsigned short g_h1a[67108864], g_h1b[67108864];     // h2 images hi/lo

__device__ __forceinline__ uint32_t s2u(const void* p) {
    uint32_t a;
    asm("{ .reg .u64 t; cvta.to.shared.u64 t, %1; cvt.u32.u64 %0, t; }" : "=r"(a) : "l"(p));
    return a;
}
__device__ __forceinline__ void ldsm4(uint32_t* r, uint32_t a) {
    asm volatile("ldmatrix.sync.aligned.m8n8.x4.shared.b16 {%0,%1,%2,%3}, [%4];"
                 : "=r"(r[0]), "=r"(r[1]), "=r"(r[2]), "=r"(r[3]) : "r"(a));
}
__device__ __forceinline__ void mma16816(float* c, const uint32_t* a, uint32_t b0, uint32_t b1) {
    asm volatile("mma.sync.aligned.m16n8k16.row.col.f32.bf16.bf16.f32 "
                 "{%0,%1,%2,%3},{%4,%5,%6,%7},{%8,%9},{%0,%1,%2,%3};"
                 : "+f"(c[0]), "+f"(c[1]), "+f"(c[2]), "+f"(c[3])
                 : "r"(a[0]), "r"(a[1]), "r"(a[2]), "r"(a[3]), "r"(b0), "r"(b1));
}
__device__ __forceinline__ uint32_t packhi(float f0, float f1, float& h0f, float& h1f) {
    __nv_bfloat16 h0 = __float2bfloat16(f0), h1 = __float2bfloat16(f1);
    h0f = __bfloat162float(h0);
    h1f = __bfloat162float(h1);
    return (uint32_t)__bfloat16_as_ushort(h0) | ((uint32_t)__bfloat16_as_ushort(h1) << 16);
}
__device__ __forceinline__ uint32_t packlo(float r0, float r1) {
    __nv_bfloat16 l0 = __float2bfloat16(r0), l1 = __float2bfloat16(r1);
    return (uint32_t)__bfloat16_as_ushort(l0) | ((uint32_t)__bfloat16_as_ushort(l1) << 16);
}
__device__ __forceinline__ void cpa16(uint32_t s, const void* g) {
    asm volatile("cp.async.cg.shared.global [%0], [%1], 16;" :: "r"(s), "l"(g) : "memory");
}

// -------- weight prep: bf16 hi/lo split, pre-swizzled [128n][64k] tiles, image idx kc*4+nb --------
__global__ void prep_w(const float* __restrict__ W,
                       unsigned short* __restrict__ dh, unsigned short* __restrict__ dl) {
    int idx = blockIdx.x * 256 + threadIdx.x;
    int n = idx & 511, k = idx >> 9;
    float f = W[idx];
    __nv_bfloat16 h = __float2bfloat16(f);
    float hf = __bfloat162float(h);
    __nv_bfloat16 l = __float2bfloat16(f - hf);
    int nb = n >> 7, nl = n & 127, kc = k >> 6, kl = k & 63;
    uint32_t off = (uint32_t)(kc * 4 + nb) * 8192u + (SWZ((uint32_t)(nl * 128 + kl * 2)) >> 1);
    dh[off] = __bfloat16_as_ushort(h);
    dl[off] = __bfloat16_as_ushort(l);
}

// -------- Z prep: koopman -> swizzled hi/lo A images ([128row][64k] per rowtile) --------
__global__ void prep_z(const float* __restrict__ koop,
                       unsigned short* __restrict__ zh, unsigned short* __restrict__ zl) {
    int idx = blockIdx.x * 256 + threadIdx.x;   // 1,048,576 total
    int r = idx >> 3, kg = (idx & 7) * 8;
    const float* s = koop + (r >> 6) * 4096 + (r & 63);
    uint32_t hi[4], lo[4];
#pragma unroll
    for (int j = 0; j < 4; j++) {
        float f0 = s[(kg + 2 * j) * 64], f1 = s[(kg + 2 * j + 1) * 64];
        float h0f, h1f;
        hi[j] = packhi(f0, f1, h0f, h1f);
        lo[j] = packlo(f0 - h0f, f1 - h1f);
    }
    int rt = r >> 7, rl = r & 127;
    uint32_t off = SWZ((uint32_t)(rl * 128 + kg * 2));
    size_t ob = (size_t)rt * 8192 + (off >> 1);
    *(uint4*)(zh + ob) = make_uint4(hi[0], hi[1], hi[2], hi[3]);
    *(uint4*)(zl + ob) = make_uint4(lo[0], lo[1], lo[2], lo[3]);
}

// -------- GEMM layer: tanh(A @ W + bias); A/B from pre-swizzled images via cp.async --------
// Output: either swizzled hi/lo images (ohi/olo) or fp32 col-major (ofp).
__global__ void __launch_bounds__(512, 1) gemm_layer(
    const unsigned short* __restrict__ ahi, const unsigned short* __restrict__ alo,
    int kin,
    const unsigned short* __restrict__ wh, const unsigned short* __restrict__ wl,
    const float* __restrict__ bias,
    unsigned short* __restrict__ ohi, unsigned short* __restrict__ olo,
    float* __restrict__ ofp) {
    extern __shared__ char sm[];
    const uint32_t sb = s2u(sm);
    const int tid = threadIdx.x, lane = tid & 31, wid = tid >> 5;
    const int wm = wid & 3, wn = wid >> 2;
    const int nb = blockIdx.x, rt = blockIdx.y;
    float* bs = (float*)(sm + 131072);
    if (tid < 128) bs[tid] = bias[nb * 128 + tid];

    const int nchunk = kin >> 6;
    const unsigned short* abh = ahi + (size_t)rt * nchunk * 8192;
    const unsigned short* abl = alo + (size_t)rt * nchunk * 8192;

    auto prefetch = [&](int kc, int b) {
        uint32_t dbase = sb + b * 65536;
        const char* s0 = (const char*)(abh + kc * 8192);
        const char* s1 = (const char*)(abl + kc * 8192);
        const char* s2 = (const char*)(wh + (size_t)(kc * 4 + nb) * 8192);
        const char* s3 = (const char*)(wl + (size_t)(kc * 4 + nb) * 8192);
#pragma unroll
        for (int i = 0; i < 8; i++) {
            int u = tid + i * 512;
            int sec = u >> 10;
            int off = (u & 1023) * 16;
            const char* src = (sec == 0) ? s0 : (sec == 1) ? s1 : (sec == 2) ? s2 : s3;
            cpa16(dbase + sec * 16384 + off, src + off);
        }
    };

    float acc[2][4][4];
#pragma unroll
    for (int t = 0; t < 2; t++)
#pragma unroll
        for (int o = 0; o < 4; o++)
#pragma unroll
            for (int q = 0; q < 4; q++) acc[t][o][q] = 0.f;

    const int a_row = wm * 32 + (lane & 15);
    const int a_kb = (lane >> 4) * 16;
    const int b_nrow = wn * 32 + (lane & 7) + ((lane >> 4) << 3);
    const int b_kb = ((lane >> 3) & 1) * 16;

    prefetch(0, 0);
    asm volatile("cp.async.commit_group;" ::: "memory");

    for (int kc = 0; kc < nchunk; kc++) {
        int b = kc & 1;
        if (kc + 1 < nchunk) {
            prefetch(kc + 1, b ^ 1);
            asm volatile("cp.async.commit_group;" ::: "memory");
            asm volatile("cp.async.wait_group 1;" ::: "memory");
        } else {
            asm volatile("cp.async.wait_group 0;" ::: "memory");
        }
        __syncthreads();
        const uint32_t SA = sb + b * 65536;
        const uint32_t SAH = SA, SAL = SA + 16384, SBH = SA + 32768, SBL = SA + 49152;
#pragma unroll
        for (int kk = 0; kk < 4; kk++) {
            uint32_t ah[2][4], al[2][4];
#pragma unroll
            for (int t = 0; t < 2; t++) {
                uint32_t ro = (uint32_t)((a_row + t * 16) * 128 + kk * 32 + a_kb);
                ldsm4(ah[t], SAH + SWZ(ro));
                ldsm4(al[t], SAL + SWZ(ro));
            }
#pragma unroll
            for (int g = 0; g < 2; g++) {
                uint32_t ro = (uint32_t)((b_nrow + g * 16) * 128 + kk * 32 + b_kb);
                uint32_t bh[4], bl[4];
                ldsm4(bh, SBH + SWZ(ro));
#pragma unroll
                for (int t = 0; t < 2; t++) {
                    mma16816(acc[t][2 * g], ah[t], bh[0], bh[1]);
                    mma16816(acc[t][2 * g + 1], ah[t], bh[2], bh[3]);
                    mma16816(acc[t][2 * g], al[t], bh[0], bh[1]);
                    mma16816(acc[t][2 * g + 1], al[t], bh[2], bh[3]);
                }
                ldsm4(bl, SBL + SWZ(ro));
#pragma unroll
                for (int t = 0; t < 2; t++) {
                    mma16816(acc[t][2 * g], ah[t], bl[0], bl[1]);
                    mma16816(acc[t][2 * g + 1], ah[t], bl[2], bl[3]);
                }
            }
        }
        __syncthreads();
    }

    // ---- epilogue: bias + tanh -> smem bounce (overlays dead buffers) ----
    float* S = (float*)sm;
#pragma unroll
    for (int t = 0; t < 2; t++) {
        int rl = wm * 32 + t * 16 + (lane >> 2);
#pragma unroll
        for (int o = 0; o < 4; o++) {
            int cl = wn * 32 + o * 8 + (lane & 3) * 2;
            float b0 = bs[cl], b1 = bs[cl + 1];
            S[rl * 132 + cl] = tanhf(acc[t][o][0] + b0);
            S[rl * 132 + cl + 1] = tanhf(acc[t][o][1] + b1);
            S[(rl + 8) * 132 + cl] = tanhf(acc[t][o][2] + b0);
            S[(rl + 8) * 132 + cl + 1] = tanhf(acc[t][o][3] + b1);
        }
    }
    __syncthreads();
    if (ofp) {
        const int mbase = rt * 128;
        for (int p = tid; p < 16384; p += 512) {
            int row = p & 127, c = p >> 7;
            ofp[(size_t)(nb * 128 + c) * MTOT + mbase + row] = S[row * 132 + c];
        }
    } else {
        for (int u = tid; u < 2048; u += 512) {
            int kcg = u >> 10;
            int d = (u & 1023) * 16;                 // byte offset in 16KB image
            int olog = SWZ(d);
            int row = olog >> 7, k0 = (olog & 127) >> 1;
            const float* sp = S + row * 132 + kcg * 64 + k0;
            uint32_t hi[4], lo[4];
#pragma unroll
            for (int j = 0; j < 4; j++) {
                float h0f, h1f;
                hi[j] = packhi(sp[2 * j], sp[2 * j + 1], h0f, h1f);
                lo[j] = packlo(sp[2 * j] - h0f, sp[2 * j + 1] - h1f);
            }
            size_t ob = ((size_t)rt * 8 + nb * 2 + kcg) * 8192 + (d >> 1);
            *(uint4*)(ohi + ob) = make_uint4(hi[0], hi[1], hi[2], hi[3]);
            *(uint4*)(olo + ob) = make_uint4(lo[0], lo[1], lo[2], lo[3]);
        }
    }
}

// -------- layer-4 diagonal + final combine --------
__global__ void diag_kernel(const float* __restrict__ h3, const float* __restrict__ W4,
                            const float* __restrict__ b4, const float* __restrict__ x,
                            float* __restrict__ ds, float* __restrict__ out, int mode) {
    int r = blockIdx.x * 256 + threadIdx.x;
    int i = r & 63;
    float acc = 0.f;
#pragma unroll 8
    for (int c = 0; c < 512; c++)
        acc += h3[(size_t)c * MTOT + r] * W4[c * 64 + i];
    acc += b4[i];
    if (mode == 0) ds[r] = acc;
    else out[r] = (x[r] - acc) * expf(-ds[r]);
}

extern "C" void kernel_launch(void* const* d_in, const int* in_sizes, int n_in,
                              void* d_out, int out_size) {
    const float* x = (const float*)d_in[0];
    const float* koop = (const float*)d_in[1];
    const float *W[8], *Bs[8];
    for (int i = 0; i < 8; i++) {
        W[i] = (const float*)d_in[2 + 2 * i];
        Bs[i] = (const float*)d_in[3 + 2 * i];
    }
    unsigned short *wh, *wl, *zh, *zl, *h0a, *h0b, *h1a, *h1b;
    float *act, *ds;
    cudaGetSymbolAddress((void**)&wh, g_whi);
    cudaGetSymbolAddress((void**)&wl, g_wlo);
    cudaGetSymbolAddress((void**)&zh, g_zhi);
    cudaGetSymbolAddress((void**)&zl, g_zlo);
    cudaGetSymbolAddress((void**)&h0a, g_h0a);
    cudaGetSymbolAddress((void**)&h0b, g_h0b);
    cudaGetSymbolAddress((void**)&h1a, g_h1a);
    cudaGetSymbolAddress((void**)&h1b, g_h1b);
    cudaGetSymbolAddress((void**)&act, g_act);
    cudaGetSymbolAddress((void**)&ds, g_ds);
    cudaFuncSetAttribute(gemm_layer, cudaFuncAttributeMaxDynamicSharedMemorySize, SMEMSZ);

    const int off[6] = {0, 32768, 294912, 557056, 589824, 851968};
    const float* wsrc[6] = {W[0], W[1], W[2], W[4], W[5], W[6]};
    for (int i = 0; i < 6; i++) {
        int kin = (i % 3 == 0) ? 64 : 512;
        prep_w<<<kin * 512 / 256, 256>>>(wsrc[i], wh + off[i], wl + off[i]);
    }
    prep_z<<<4096, 256>>>(koop, zh, zl);

    dim3 grid(4, 1024);
    for (int chain = 0; chain < 2; chain++) {
        int o0 = chain * 3;
        gemm_layer<<<grid, 512, SMEMSZ>>>(zh, zl, 64, wh + off[o0], wl + off[o0],
                                          Bs[chain * 4 + 0], h0a, h0b, nullptr);
        gemm_layer<<<grid, 512, SMEMSZ>>>(h0a, h0b, 512, wh + off[o0 + 1], wl + off[o0 + 1],
                                          Bs[chain * 4 + 1], h1a, h1b, nullptr);
        gemm_layer<<<grid, 512, SMEMSZ>>>(h1a, h1b, 512, wh + off[o0 + 2], wl + off[o0 + 2],
                                          Bs[chain * 4 + 2], nullptr, nullptr, act);
        diag_kernel<<<512, 256>>>(act, W[chain * 4 + 3], Bs[chain * 4 + 3], x, ds,
                                  (float*)d_out, chain);
    }
}